// round 8
// baseline (speedup 1.0000x reference)
#include <cuda_runtime.h>
#include <cuda_bf16.h>

typedef unsigned long long u64;

// ---- f32x2 packed-FMA helpers (sm_103a; FFMA2 only reachable via PTX) ----
__device__ __forceinline__ void ffma2(u64 &acc, u64 a, u64 b) {
    asm("fma.rn.f32x2 %0, %1, %2, %0;" : "+l"(acc) : "l"(a), "l"(b));
}
__device__ __forceinline__ u64 pack2(float x, float y) {
    u64 r; asm("mov.b64 %0, {%1, %2};" : "=l"(r) : "f"(x), "f"(y)); return r;
}
__device__ __forceinline__ float2 unpack2(u64 v) {
    float2 f; asm("mov.b64 {%0, %1}, %2;" : "=f"(f.x), "=f"(f.y) : "l"(v)); return f;
}
__device__ __forceinline__ float tanh_fast(float x) {
    float r; asm("tanh.approx.f32 %0, %1;" : "=f"(r) : "f"(x)); return r;
}

// Problem constants
static constexpr int D  = 1024;   // feature dim
static constexpr int DR = 64;     // inner dim
static constexpr int T  = 64;     // threads per block (T * 8 groups == 512 == NG)
// Each thread owns 8 CONSECUTIVE groups n = 8*tid .. 8*tid+7, processed as 4
// f32x2 pairs p = 0..3: pair lanes = (group 8t+2p, group 8t+2p+1).
// Windows span xs[16t .. 16t+23] (24 floats). Packed operand
//   ext[f] = (xs[16t+f], xs[16t+f+2]),  f = 0..21
// serves pair p at features j: operand = ext[4p + j], j = 0..9.
// Halo: xs[i] = x[(i-4) mod D], so x[16t+k] = xs[16t+4+k] = v[4+k].

__global__ void __launch_bounds__(T)
parallel_euler_kernel(const float* __restrict__ x,
                      const float* __restrict__ W_in,   // [64,10] row-major
                      const float* __restrict__ b_in,   // [64]
                      const float* __restrict__ W_out,  // [2,64] row-major
                      float* __restrict__ out) {
    __shared__ __align__(16) float xs[D + 32];
    __shared__ __align__(16) u64 wdup[DR * 10];  // (W_in[r,f], W_in[r,f])
    __shared__ __align__(16) u64 w2[DR * 2];     // [2r]=(Wo0,Wo0), [2r+1]=(Wo1,Wo1)
    __shared__ u64 bp[DR];                        // (b,b)

    const int tid = threadIdx.x;
    const float* xrow = x + (size_t)blockIdx.x * D;

    for (int i = tid; i < D + 24; i += T)
        xs[i] = xrow[(i + (D - 4)) & (D - 1)];

    for (int i = tid; i < DR * 10; i += T) {
        float w = W_in[i];
        wdup[i] = pack2(w, w);
    }
    if (tid < DR) {
        float b = b_in[tid];
        bp[tid] = pack2(b, b);
        float w0 = W_out[tid];
        float w1 = W_out[DR + tid];
        w2[2 * tid + 0] = pack2(w0, w0);
        w2[2 * tid + 1] = pack2(w1, w1);
    }
    __syncthreads();

    // Stage the 24-float footprint, build 22 packed window operands.
    const int base = 16 * tid;           // xs index of window start for group 8t
    u64 ext[22];
    float vlast[4];                      // v[20..23] not needed; keep v in regs:
    {
        const float4* xv4 = (const float4*)(xs + base);   // 16B aligned
        float v[24];
#pragma unroll
        for (int q = 0; q < 6; q++) {
            float4 t4 = xv4[q];
            v[4 * q + 0] = t4.x; v[4 * q + 1] = t4.y;
            v[4 * q + 2] = t4.z; v[4 * q + 3] = t4.w;
        }
#pragma unroll
        for (int f = 0; f < 22; f++)
            ext[f] = pack2(v[f], v[f + 2]);
        vlast[0] = v[20]; vlast[1] = v[21]; vlast[2] = v[22]; vlast[3] = v[23];
        (void)vlast;
    }

    u64 ya[4], yb[4];                    // per pair: out-ch0 lanes, out-ch1 lanes
#pragma unroll
    for (int p = 0; p < 4; p++) { ya[p] = 0ull; yb[p] = 0ull; }

#pragma unroll 2
    for (int r = 0; r < DR; r++) {
        // 10 scalar LDS.64 weight loads (broadcast, conflict-free, pair-aligned)
        const u64* wr = wdup + r * 10;
        u64 w0 = wr[0], w1 = wr[1], w2_ = wr[2], w3 = wr[3], w4 = wr[4];
        u64 w5 = wr[5], w6 = wr[6], w7 = wr[7], w8 = wr[8], w9 = wr[9];
        const u64 bb = bp[r];

        u64 a0 = bb, a1 = bb, a2 = bb, a3 = bb;
        // feature-outer, pair-inner: each weight feeds 4 independent chains
        ffma2(a0, w0, ext[0]);  ffma2(a1, w0, ext[4]);  ffma2(a2, w0, ext[8]);  ffma2(a3, w0, ext[12]);
        ffma2(a0, w1, ext[1]);  ffma2(a1, w1, ext[5]);  ffma2(a2, w1, ext[9]);  ffma2(a3, w1, ext[13]);
        ffma2(a0, w2_, ext[2]); ffma2(a1, w2_, ext[6]); ffma2(a2, w2_, ext[10]); ffma2(a3, w2_, ext[14]);
        ffma2(a0, w3, ext[3]);  ffma2(a1, w3, ext[7]);  ffma2(a2, w3, ext[11]); ffma2(a3, w3, ext[15]);
        ffma2(a0, w4, ext[4]);  ffma2(a1, w4, ext[8]);  ffma2(a2, w4, ext[12]); ffma2(a3, w4, ext[16]);
        ffma2(a0, w5, ext[5]);  ffma2(a1, w5, ext[9]);  ffma2(a2, w5, ext[13]); ffma2(a3, w5, ext[17]);
        ffma2(a0, w6, ext[6]);  ffma2(a1, w6, ext[10]); ffma2(a2, w6, ext[14]); ffma2(a3, w6, ext[18]);
        ffma2(a0, w7, ext[7]);  ffma2(a1, w7, ext[11]); ffma2(a2, w7, ext[15]); ffma2(a3, w7, ext[19]);
        ffma2(a0, w8, ext[8]);  ffma2(a1, w8, ext[12]); ffma2(a2, w8, ext[16]); ffma2(a3, w8, ext[20]);
        ffma2(a0, w9, ext[9]);  ffma2(a1, w9, ext[13]); ffma2(a2, w9, ext[17]); ffma2(a3, w9, ext[21]);

        const u64 wo0 = w2[2 * r + 0];
        const u64 wo1 = w2[2 * r + 1];
        {
            float2 f = unpack2(a0);
            u64 h = pack2(tanh_fast(f.x), tanh_fast(f.y));
            ffma2(ya[0], wo0, h); ffma2(yb[0], wo1, h);
        }
        {
            float2 f = unpack2(a1);
            u64 h = pack2(tanh_fast(f.x), tanh_fast(f.y));
            ffma2(ya[1], wo0, h); ffma2(yb[1], wo1, h);
        }
        {
            float2 f = unpack2(a2);
            u64 h = pack2(tanh_fast(f.x), tanh_fast(f.y));
            ffma2(ya[2], wo0, h); ffma2(yb[2], wo1, h);
        }
        {
            float2 f = unpack2(a3);
            u64 h = pack2(tanh_fast(f.x), tanh_fast(f.y));
            ffma2(ya[3], wo0, h); ffma2(yb[3], wo1, h);
        }
    }

    // Residual + store: pair p covers out[base' + 4p .. base'+4p+3], base' = 16t.
    // x values: x[16t+4p+k] = v[4+4p+k]: (ext[4+4p].x, ext[5+4p].x, ext[4+4p].y, ext[5+4p].y)
    float* orow = out + (size_t)blockIdx.x * D + base;
#pragma unroll
    for (int p = 0; p < 4; p++) {
        float2 ea = unpack2(ext[4 + 4 * p]);   // (x[.. +0], x[.. +2])
        float2 eb = unpack2(ext[5 + 4 * p]);   // (x[.. +1], x[.. +3])
        float2 a = unpack2(ya[p]);             // ch0 of (group 2p, 2p+1)
        float2 b = unpack2(yb[p]);             // ch1
        *(float4*)(orow + 4 * p) =
            make_float4(ea.x + a.x, eb.x + b.x, ea.y + a.y, eb.y + b.y);
    }
}

extern "C" void kernel_launch(void* const* d_in, const int* in_sizes, int n_in,
                              void* d_out, int out_size) {
    const float* x     = (const float*)d_in[0];
    const float* W_in  = (const float*)d_in[1];
    const float* b_in  = (const float*)d_in[2];
    const float* W_out = (const float*)d_in[3];
    // d_in[4] (idx) unused: the index pattern is the fixed ring window.
    float* out = (float*)d_out;

    const int batch = in_sizes[0] / D;
    parallel_euler_kernel<<<batch, T>>>(x, W_in, b_in, W_out, out);
}

// round 9
// speedup vs baseline: 1.2235x; 1.2235x over previous
#include <cuda_runtime.h>
#include <cuda_bf16.h>

typedef unsigned long long u64;

// ---- f32x2 packed helpers (sm_103a; f32x2 ops only reachable via PTX) ----
__device__ __forceinline__ void ffma2(u64 &acc, u64 a, u64 b) {
    asm("fma.rn.f32x2 %0, %1, %2, %0;" : "+l"(acc) : "l"(a), "l"(b));
}
__device__ __forceinline__ u64 fadd2(u64 a, u64 b) {
    u64 r; asm("add.rn.f32x2 %0, %1, %2;" : "=l"(r) : "l"(a), "l"(b)); return r;
}
__device__ __forceinline__ u64 pack2(float x, float y) {
    u64 r; asm("mov.b64 %0, {%1, %2};" : "=l"(r) : "f"(x), "f"(y)); return r;
}
__device__ __forceinline__ float2 unpack2(u64 v) {
    float2 f; asm("mov.b64 {%0, %1}, %2;" : "=f"(f.x), "=f"(f.y) : "l"(v)); return f;
}
__device__ __forceinline__ float tanh_fast(float x) {
    float r; asm("tanh.approx.f32 %0, %1;" : "=f"(r) : "f"(x)); return r;
}

// Problem constants
static constexpr int D  = 1024;   // feature dim
static constexpr int DR = 64;     // inner dim
static constexpr int T  = 128;    // threads per block
// Each thread owns 4 CONSECUTIVE groups n0..n0+3 (n0 = 4*tid), feature-paired
// lanes (R1 formulation): acc lane = (feature 2j, 2j+1) of one group, operands
// come DIRECTLY from shared as LDS.64 (no register packing -> no ALU storms).
// Window of group n = xs2[n .. n+4]; 4 consecutive groups share xs2[n0..n0+7]
// (8 u64 registers instead of R1's 20).
// Halo: xs[i] = x[(i-4) mod D]  =>  xs2[k] = (x[2k-4], x[2k-3]);
// residual x[2n], x[2n+1] = xs2[n+2].

__global__ void __launch_bounds__(T)
parallel_euler_kernel(const float* __restrict__ x,
                      const float* __restrict__ W_in,   // [64,10] row-major
                      const float* __restrict__ b_in,   // [64]
                      const float* __restrict__ W_out,  // [2,64] row-major
                      float* __restrict__ out) {
    __shared__ __align__(16) float xs[D + 16];
    __shared__ __align__(16) u64 wrow[DR * 5];  // (W_in[r,2j], W_in[r,2j+1])
    __shared__ u64 bp[DR];                       // (b_in[r], 0)  -> hsum fold
    __shared__ u64 wop[DR];                      // (W_out[0,r], W_out[1,r])

    const int tid = threadIdx.x;
    const float* xrow = x + (size_t)blockIdx.x * D;

    for (int i = tid; i < D + 12; i += T)
        xs[i] = xrow[(i + (D - 4)) & (D - 1)];

    // W_in rows: 10 floats = 5 u64, pairs 8B-aligned in global — direct copy.
    for (int k = tid; k < DR * 5; k += T)
        wrow[k] = ((const u64*)W_in)[k];

    if (tid < DR) {
        bp[tid]  = pack2(b_in[tid], 0.0f);
        wop[tid] = pack2(W_out[tid], W_out[DR + tid]);
    }
    __syncthreads();

    // Shared window: 8 LDS.64, all loop-invariant, held in 16 regs.
    const int n0 = 4 * tid;
    const u64* xs2 = (const u64*)xs;
    u64 win[8];
#pragma unroll
    for (int k = 0; k < 8; k++)
        win[k] = xs2[n0 + k];

    u64 yg0 = 0ull, yg1 = 0ull, yg2 = 0ull, yg3 = 0ull;  // (ch0,ch1) per group

#pragma unroll 4
    for (int r = 0; r < DR; r++) {
        const u64* wr = &wrow[r * 5];
        u64 a0 = bp[r];                 // (b, 0): bias + horizontal-add fold
        u64 a1 = a0, a2 = a0, a3 = a0;
#pragma unroll
        for (int j = 0; j < 5; j++) {
            const u64 w = wr[j];        // broadcast LDS.64, conflict-free
            ffma2(a0, w, win[0 + j]);
            ffma2(a1, w, win[1 + j]);
            ffma2(a2, w, win[2 + j]);
            ffma2(a3, w, win[3 + j]);
        }
        const u64 wo = wop[r];          // (Wo0, Wo1)
        {
            float2 f = unpack2(a0);
            float h = tanh_fast(f.x + f.y);
            ffma2(yg0, wo, pack2(h, h));
        }
        {
            float2 f = unpack2(a1);
            float h = tanh_fast(f.x + f.y);
            ffma2(yg1, wo, pack2(h, h));
        }
        {
            float2 f = unpack2(a2);
            float h = tanh_fast(f.x + f.y);
            ffma2(yg2, wo, pack2(h, h));
        }
        {
            float2 f = unpack2(a3);
            float h = tanh_fast(f.x + f.y);
            ffma2(yg3, wo, pack2(h, h));
        }
    }

    // Residual + store: group n -> out[2n],out[2n+1]; x-pair = win[g+2].
    u64* orow2 = (u64*)(out + (size_t)blockIdx.x * D);
    orow2[n0 + 0] = fadd2(win[2], yg0);
    orow2[n0 + 1] = fadd2(win[3], yg1);
    orow2[n0 + 2] = fadd2(win[4], yg2);
    orow2[n0 + 3] = fadd2(win[5], yg3);
}

extern "C" void kernel_launch(void* const* d_in, const int* in_sizes, int n_in,
                              void* d_out, int out_size) {
    const float* x     = (const float*)d_in[0];
    const float* W_in  = (const float*)d_in[1];
    const float* b_in  = (const float*)d_in[2];
    const float* W_out = (const float*)d_in[3];
    // d_in[4] (idx) unused: the index pattern is the fixed ring window.
    float* out = (float*)d_out;

    const int batch = in_sizes[0] / D;
    parallel_euler_kernel<<<batch, T>>>(x, W_in, b_in, W_out, out);
}